// round 14
// baseline (speedup 1.0000x reference)
#include <cuda_runtime.h>
#include <cuda_bf16.h>
#include <cuda_fp16.h>
#include <cstdint>

#define B_    32
#define N_    8
#define CIN   3
#define HWD   224
#define PATCH 32
#define S_    49
#define C_    384
#define HM_   512
#define CO_   256
#define NP    12544
#define KCONV 3072
#define NE    2048
#define NAG   1024
#define NODE0 (NE * 7 + NE)
#define NODEZ (B_ * N_ * 3600)

// ---- scratch (static device globals; no allocation) ----
__device__ __align__(16) __half g_Wph[C_ * KCONV];
__device__ __align__(16) __half g_W1t_h[NAG * C_];
__device__ __align__(16) __half g_feats_h[NP * C_];
__device__ __align__(16) __half g_a[NP * HM_];     // includes +b1
__device__ __align__(16) __half g_g[NP * HM_];
__device__ float g_mask[NE];
__device__ float g_W2h[HM_ * 7];
__device__ float g_bias7[7];

// ---- helpers ----
__device__ __forceinline__ uint32_t smem_to_u32(const void* p) {
    uint32_t a;
    asm("{ .reg .u64 t; cvta.to.shared.u64 t, %1; cvt.u32.u64 %0, t; }" : "=r"(a) : "l"(p));
    return a;
}
__device__ __forceinline__ void cp16(uint32_t dst, const void* src) {
    asm volatile("cp.async.cg.shared.global [%0], [%1], 16;" :: "r"(dst), "l"(src));
}
#define CP_COMMIT() asm volatile("cp.async.commit_group;" ::: "memory")
#define CP_WAIT1()  asm volatile("cp.async.wait_group 1;" ::: "memory")
#define CP_WAIT0()  asm volatile("cp.async.wait_group 0;" ::: "memory")

__device__ __forceinline__ void ldm4(uint32_t* r, uint32_t addr) {
    asm volatile("ldmatrix.sync.aligned.m8n8.x4.shared.b16 {%0,%1,%2,%3}, [%4];"
                 : "=r"(r[0]), "=r"(r[1]), "=r"(r[2]), "=r"(r[3]) : "r"(addr));
}
__device__ __forceinline__ void mma_f16(float* c, const uint32_t* a,
                                        uint32_t b0, uint32_t b1) {
    asm volatile(
        "mma.sync.aligned.m16n8k16.row.col.f32.f16.f16.f32 "
        "{%0,%1,%2,%3}, {%4,%5,%6,%7}, {%8,%9}, {%0,%1,%2,%3};"
        : "+f"(c[0]), "+f"(c[1]), "+f"(c[2]), "+f"(c[3])
        : "r"(a[0]), "r"(a[1]), "r"(a[2]), "r"(a[3]), "r"(b0), "r"(b1));
}
__device__ __forceinline__ uint32_t h2pack(float x, float y) {
    __half2 h = __floats2half2_rn(x, y);
    return *reinterpret_cast<uint32_t*>(&h);
}

// smem rows: 32 fp16 (64B) padded to 80B (conflict-free mod 128)
#define ROWB    80
#define TILE_B  (128 * ROWB)
#define G_STAGE  (2 * TILE_B)
#define G_SMEM   (3 * G_STAGE)
#define GOFF_A   0
#define GOFF_B   TILE_B

// ============================================================
// Fused prep: w2h | mask | wp | w1-transpose | node-zeros
// ============================================================
#define PB_W2H  64
#define PB_MASK 8
#define PB_WP   ((C_ * KCONV / 4) / 256)
#define PB_W1T  ((NAG / 64) * (C_ / 64))
#define PB_ZERO (NODEZ / (256 * 16))
#define PB_TOTAL (PB_W2H + PB_MASK + PB_WP + PB_W1T + PB_ZERO)

__device__ __forceinline__ float head_w(int o, int k,
                                        const float* Wph, const float* Wpv,
                                        const float* Wr, const float* Wrv)
{
    if (k < 2) return Wph[o * 2 + k];
    if (k < 4) return Wpv[o * 2 + (k - 2)];
    if (k < 6) return Wr[o * 2 + (k - 4)];
    return Wrv[o];
}

__global__ void __launch_bounds__(256)
prep_all_kernel(const float* __restrict__ pos,
                const float* __restrict__ Wp,
                const float* __restrict__ W1a, const float* __restrict__ W1b,
                const float* __restrict__ W2,  const float* __restrict__ b2,
                const float* __restrict__ Wph, const float* __restrict__ bph,
                const float* __restrict__ Wpv, const float* __restrict__ bpv,
                const float* __restrict__ Wr,  const float* __restrict__ br,
                const float* __restrict__ Wrv, const float* __restrict__ brv,
                float* __restrict__ out)
{
    __shared__ float ts[64][65];
    float (*sW)[7] = (float (*)[7])&ts[0][0];
    int bid = blockIdx.x;
    const int tid = threadIdx.x;

    if (bid < PB_W2H) {
        const int lane = tid & 31, wid = tid >> 5;
        if (tid < CO_) {
#pragma unroll
            for (int k = 0; k < 7; k++)
                sW[tid][k] = head_w(tid, k, Wph, Wpv, Wr, Wrv);
        }
        __syncthreads();
        const int h = bid * 8 + wid;
        float acc[7] = {0, 0, 0, 0, 0, 0, 0};
#pragma unroll
        for (int t = 0; t < 8; t++) {
            int o = lane + 32 * t;
            float w2 = W2[h * CO_ + o];
#pragma unroll
            for (int k = 0; k < 7; k++)
                acc[k] = fmaf(w2, sW[o][k], acc[k]);
        }
#pragma unroll
        for (int k = 0; k < 7; k++) {
#pragma unroll
            for (int off = 16; off; off >>= 1)
                acc[k] += __shfl_down_sync(0xffffffffu, acc[k], off);
        }
        if (lane == 0) {
#pragma unroll
            for (int k = 0; k < 7; k++)
                g_W2h[h * 7 + k] = acc[k] * (1.0f / 49.0f);
        }
        if (bid == 0 && tid < 7) {
            float sum = 0.f;
            for (int o = 0; o < CO_; o++)
                sum = fmaf(b2[o], sW[o][tid], sum);
            float bb = (tid < 2) ? bph[tid] : (tid < 4) ? bpv[tid - 2]
                     : (tid < 6) ? br[tid - 4] : brv[0];
            g_bias7[tid] = sum + bb;
        }
        return;
    }
    bid -= PB_W2H;

    if (bid < PB_MASK) {
        int e = bid * 256 + tid;
        int b = e >> 6, i = (e >> 3) & 7, j = e & 7;
        float xi = pos[(b * N_ + i) * 3 + 0], yi = pos[(b * N_ + i) * 3 + 1];
        float xj = pos[(b * N_ + j) * 3 + 0], yj = pos[(b * N_ + j) * 3 + 1];
        float dx = xi - xj, dy = yi - yj;
        float d2 = __fadd_rn(__fmul_rn(dx, dx), __fmul_rn(dy, dy));
        float m = (d2 < 0.25f && i != j) ? 1.0f : 0.0f;
        g_mask[e] = m;
        out[NE * 7 + e] = m;
        return;
    }
    bid -= PB_MASK;

    if (bid < PB_WP) {
        int i4 = bid * 256 + tid;
        float4 v = *(const float4*)&Wp[(long)i4 * 4];
        *(uint2*)&g_Wph[(long)i4 * 4] = make_uint2(h2pack(v.x, v.y), h2pack(v.z, v.w));
        return;
    }
    bid -= PB_WP;

    if (bid < PB_W1T) {
        int nt = bid / (C_ / 64);
        int kt = bid - nt * (C_ / 64);
        int n0 = nt * 64, k0 = kt * 64;
#pragma unroll
        for (int it = 0; it < 16; it++) {
            int idx = it * 256 + tid;
            int kk = idx >> 6, nn = idx & 63;
            int n = n0 + nn;
            float v = (n < HM_) ? W1a[(k0 + kk) * HM_ + n]
                                : W1b[(k0 + kk) * HM_ + (n - HM_)];
            ts[kk][nn] = v;
        }
        __syncthreads();
#pragma unroll
        for (int it = 0; it < 16; it++) {
            int idx = it * 256 + tid;
            int nn = idx >> 6, kk = idx & 63;
            g_W1t_h[(n0 + nn) * C_ + k0 + kk] = __float2half_rn(ts[kk][nn]);
        }
        return;
    }
    bid -= PB_W1T;

    {   // node_preds zeros
        int base = NODE0 + (bid * 256 + tid) * 16;
        float4 z = make_float4(0.f, 0.f, 0.f, 0.f);
        *(float4*)&out[base]      = z;
        *(float4*)&out[base + 4]  = z;
        *(float4*)&out[base + 8]  = z;
        *(float4*)&out[base + 12] = z;
    }
}

// ============================================================
// Patch GEMM: A = fp32 img, LDG prefetch depth 2, inline cvt->STS.
// B: 3-stage cp.async. grid (3, 98).
// ============================================================
__global__ void __launch_bounds__(256, 2)
patch_mma_kernel(const float* __restrict__ img, const float* __restrict__ bp)
{
    extern __shared__ __align__(128) char smem[];
    const uint32_t sb = smem_to_u32(smem);
    const int tid = threadIdx.x, lane = tid & 31, w = tid >> 5;
    const int wm = w >> 2, wn = w & 3;
    const int bn = blockIdx.x * 128, bm = blockIdx.y * 128;

    const int lrow = tid >> 1, lseg = tid & 1;
    int abase;
    {
        int p  = bm + lrow;
        int n  = p / 49;
        int s  = p - n * 49;
        int py = s / 7, px = s - py * 7;
        abase = (n * CIN * HWD + py * PATCH) * HWD + px * PATCH + lseg * 16;
    }
    const long brow = (long)(bn + lrow) * KCONV + lseg * 16;

    float acc[4][4][4];
#pragma unroll
    for (int mi = 0; mi < 4; mi++)
#pragma unroll
        for (int ni = 0; ni < 4; ni++)
#pragma unroll
            for (int t = 0; t < 4; t++) acc[mi][ni][t] = 0.f;

    float4 areg[2][4];

    auto ldA = [&](int c, int buf) {
        int k  = c * 32;
        int ci = k >> 10, rem = k & 1023, y = rem >> 5;
        const float4* src = (const float4*)(img + abase + ci * (HWD * HWD) + y * HWD);
        areg[buf][0] = src[0]; areg[buf][1] = src[1];
        areg[buf][2] = src[2]; areg[buf][3] = src[3];
    };
    auto stA = [&](int st, int buf) {
        uint32_t ad = sb + st * G_STAGE + GOFF_A + lrow * ROWB + lseg * 32;
        uint4 v0 = make_uint4(h2pack(areg[buf][0].x, areg[buf][0].y),
                              h2pack(areg[buf][0].z, areg[buf][0].w),
                              h2pack(areg[buf][1].x, areg[buf][1].y),
                              h2pack(areg[buf][1].z, areg[buf][1].w));
        uint4 v1 = make_uint4(h2pack(areg[buf][2].x, areg[buf][2].y),
                              h2pack(areg[buf][2].z, areg[buf][2].w),
                              h2pack(areg[buf][3].x, areg[buf][3].y),
                              h2pack(areg[buf][3].z, areg[buf][3].w));
        asm volatile("st.shared.v4.b32 [%0], {%1,%2,%3,%4};"
                     :: "r"(ad), "r"(v0.x), "r"(v0.y), "r"(v0.z), "r"(v0.w));
        asm volatile("st.shared.v4.b32 [%0], {%1,%2,%3,%4};"
                     :: "r"(ad + 16), "r"(v1.x), "r"(v1.y), "r"(v1.z), "r"(v1.w));
    };
    auto cpB = [&](int c, int st) {
        int k = c * 32;
        const __half* bsrc = g_Wph + brow + k;
        uint32_t bd = sb + st * G_STAGE + GOFF_B + lrow * ROWB + lseg * 32;
        cp16(bd, bsrc);
        cp16(bd + 16, bsrc + 8);
    };

    const int NC = KCONV / 32;   // 96
    ldA(0, 0);
    ldA(1, 1);
    cpB(0, 0); CP_COMMIT();
    cpB(1, 1); CP_COMMIT();

    int st = 0;
#pragma unroll 1
    for (int c = 0; c < NC; c++) {
        stA(st, c & 1);
        if (c + 1 < NC) { CP_WAIT1(); } else { CP_WAIT0(); }
        __syncthreads();
        if (c + 2 < NC) {
            int st2 = st + 2; if (st2 >= 3) st2 -= 3;
            cpB(c + 2, st2);
            CP_COMMIT();
            ldA(c + 2, c & 1);   // refill the buffer just consumed by stA
        }
        {
            const uint32_t sbase = sb + st * G_STAGE;
#pragma unroll
            for (int step = 0; step < 2; step++) {
                const uint32_t co = (uint32_t)(step * 32 + (lane >> 4) * 16);
                uint32_t bf[2][4];
#pragma unroll
                for (int nj = 0; nj < 2; nj++) {
                    uint32_t ro = (uint32_t)((wn * 32 + nj * 16 + (lane & 15)) * ROWB) + co;
                    ldm4(bf[nj], sbase + GOFF_B + ro);
                }
#pragma unroll
                for (int mi = 0; mi < 4; mi++) {
                    uint32_t af[4];
                    uint32_t ro = (uint32_t)((wm * 64 + mi * 16 + (lane & 15)) * ROWB) + co;
                    ldm4(af, sbase + GOFF_A + ro);
#pragma unroll
                    for (int ni = 0; ni < 4; ni++) {
                        int nj = ni >> 1, o = ni & 1;
                        mma_f16(acc[mi][ni], af, bf[nj][o], bf[nj][o + 2]);
                    }
                }
            }
        }
        if (++st == 3) st = 0;
    }

    const int r  = lane >> 2;
    const int cc = (lane & 3) * 2;
#pragma unroll
    for (int mi = 0; mi < 4; mi++) {
#pragma unroll
        for (int ni = 0; ni < 4; ni++) {
            int m0  = bm + wm * 64 + mi * 16 + r;
            int col = bn + wn * 32 + ni * 8 + cc;
            float b0 = bp[col], b1v = bp[col + 1];
            *(uint32_t*)&g_feats_h[(long)m0 * C_ + col] =
                h2pack(acc[mi][ni][0] + b0, acc[mi][ni][1] + b1v);
            *(uint32_t*)&g_feats_h[(long)(m0 + 8) * C_ + col] =
                h2pack(acc[mi][ni][2] + b0, acc[mi][ni][3] + b1v);
        }
    }
}

// ============================================================
// a|g GEMM: fp16 1-pass, 3-stage; epilogue stores fp16 (+b1 into a)
// grid (8, 98)
// ============================================================
__global__ void __launch_bounds__(256, 2)
ag_mma_kernel(const float* __restrict__ b1)
{
    extern __shared__ __align__(128) char smem[];
    const uint32_t sb = smem_to_u32(smem);
    const int tid = threadIdx.x, lane = tid & 31, w = tid >> 5;
    const int wm = w >> 2, wn = w & 3;
    const int bn = blockIdx.x * 128, bm = blockIdx.y * 128;

    const int lrow = tid >> 1, lseg = tid & 1;
    const long arow = (long)(bm + lrow) * C_ + lseg * 16;
    const long brow = (long)(bn + lrow) * C_ + lseg * 16;

    float acc[4][4][4];
#pragma unroll
    for (int mi = 0; mi < 4; mi++)
#pragma unroll
        for (int ni = 0; ni < 4; ni++)
#pragma unroll
            for (int t = 0; t < 4; t++) acc[mi][ni][t] = 0.f;

    auto cpAB = [&](int c, int st) {
        int k = c * 32;
        const __half* asrc = g_feats_h + arow + k;
        uint32_t ad = sb + st * G_STAGE + GOFF_A + lrow * ROWB + lseg * 32;
        cp16(ad, asrc);
        cp16(ad + 16, asrc + 8);
        const __half* bsrc = g_W1t_h + brow + k;
        uint32_t bd = sb + st * G_STAGE + GOFF_B + lrow * ROWB + lseg * 32;
        cp16(bd, bsrc);
        cp16(bd + 16, bsrc + 8);
    };

    const int NC = C_ / 32;   // 12
    cpAB(0, 0); CP_COMMIT();
    cpAB(1, 1); CP_COMMIT();

    int st = 0;
#pragma unroll 1
    for (int c = 0; c < NC; c++) {
        if (c + 1 < NC) { CP_WAIT1(); } else { CP_WAIT0(); }
        __syncthreads();
        if (c + 2 < NC) {
            int st2 = st + 2; if (st2 >= 3) st2 -= 3;
            cpAB(c + 2, st2);
            CP_COMMIT();
        }
        {
            const uint32_t sbase = sb + st * G_STAGE;
#pragma unroll
            for (int step = 0; step < 2; step++) {
                const uint32_t co = (uint32_t)(step * 32 + (lane >> 4) * 16);
                uint32_t bf[2][4];
#pragma unroll
                for (int nj = 0; nj < 2; nj++) {
                    uint32_t ro = (uint32_t)((wn * 32 + nj * 16 + (lane & 15)) * ROWB) + co;
                    ldm4(bf[nj], sbase + GOFF_B + ro);
                }
#pragma unroll
                for (int mi = 0; mi < 4; mi++) {
                    uint32_t af[4];
                    uint32_t ro = (uint32_t)((wm * 64 + mi * 16 + (lane & 15)) * ROWB) + co;
                    ldm4(af, sbase + GOFF_A + ro);
#pragma unroll
                    for (int ni = 0; ni < 4; ni++) {
                        int nj = ni >> 1, o = ni & 1;
                        mma_f16(acc[mi][ni], af, bf[nj][o], bf[nj][o + 2]);
                    }
                }
            }
        }
        if (++st == 3) st = 0;
    }

    const bool isA = (bn < HM_);
    __half* dst = isA ? g_a : g_g;
    const int nb = isA ? bn : bn - HM_;
    const int r  = lane >> 2;
    const int cc = (lane & 3) * 2;
#pragma unroll
    for (int mi = 0; mi < 4; mi++) {
#pragma unroll
        for (int ni = 0; ni < 4; ni++) {
            int m0  = bm + wm * 64 + mi * 16 + r;
            int col = nb + wn * 32 + ni * 8 + cc;
            float b0 = 0.f, b1v = 0.f;
            if (isA) { b0 = b1[col]; b1v = b1[col + 1]; }
            *(uint32_t*)&dst[(long)m0 * HM_ + col] =
                h2pack(acc[mi][ni][0] + b0, acc[mi][ni][1] + b1v);
            *(uint32_t*)&dst[(long)(m0 + 8) * HM_ + col] =
                h2pack(acc[mi][ni][2] + b0, acc[mi][ni][3] + b1v);
        }
    }
}

// ============================================================
// edge kernel: block per (b, i); 256 thr = 128 h-quads x 2 j-groups
// thread owns 4 h (uint2/LDG.64 loads) and 4 j accumulators
// ============================================================
__global__ void __launch_bounds__(256)
edge_b_kernel(float* __restrict__ out)
{
    __shared__ float red[8][28];
    __shared__ float sbias[7];

    const int blk = blockIdx.x;              // 256 = 32 b x 8 i
    const int b   = blk >> 3;
    const int i   = blk & 7;
    const int tid = threadIdx.x, lane = tid & 31, wid = tid >> 5;
    const int hq  = tid & 127;               // h-quad: h = hq*4 .. hq*4+3
    const int jg  = tid >> 7;                // 0,1: j in [jg*4, jg*4+4)

    if (tid < 7) sbias[tid] = g_bias7[tid];

    const uint2* __restrict__ ap =
        (const uint2*)(g_a + ((long)(b * 8 + i) * 49) * HM_) + hq;
    const uint2* __restrict__ gp =
        (const uint2*)(g_g + ((long)(b * 8 + jg * 4) * 49) * HM_) + hq;

    float acc[4][4];
#pragma unroll
    for (int j = 0; j < 4; j++)
#pragma unroll
        for (int t = 0; t < 4; t++) acc[j][t] = 0.f;

#pragma unroll 7
    for (int s = 0; s < 49; s++) {
        const int so = s * 128;              // uint2 stride per s-row
        uint2 ar = ap[so];
        float2 a01 = __half22float2(*(const __half2*)&ar.x);
        float2 a23 = __half22float2(*(const __half2*)&ar.y);
#pragma unroll
        for (int j = 0; j < 4; j++) {
            uint2 gr = gp[j * (49 * 128) + so];
            float2 g01 = __half22float2(*(const __half2*)&gr.x);
            float2 g23 = __half22float2(*(const __half2*)&gr.y);
            acc[j][0] += fmaxf(a01.x + g01.x, 0.f);
            acc[j][1] += fmaxf(a01.y + g01.y, 0.f);
            acc[j][2] += fmaxf(a23.x + g23.x, 0.f);
            acc[j][3] += fmaxf(a23.y + g23.y, 0.f);
        }
    }

    // wv[t*7+k] = W2h[h = hq*4+t][k]: 28 contiguous floats
    float wv[28];
#pragma unroll
    for (int t = 0; t < 28; t++) wv[t] = g_W2h[hq * 28 + t];

    __syncthreads();

    float pr[28];
#pragma unroll
    for (int j = 0; j < 4; j++)
#pragma unroll
        for (int k = 0; k < 7; k++) {
            float v = acc[j][0] * wv[k];
            v = fmaf(acc[j][1], wv[7 + k], v);
            v = fmaf(acc[j][2], wv[14 + k], v);
            v = fmaf(acc[j][3], wv[21 + k], v);
            pr[j * 7 + k] = v;
        }
#pragma unroll
    for (int t = 0; t < 28; t++) {
#pragma unroll
        for (int off = 16; off; off >>= 1)
            pr[t] += __shfl_down_sync(0xffffffffu, pr[t], off);
    }
    if (lane == 0) {
#pragma unroll
        for (int t = 0; t < 28; t++) red[wid][t] = pr[t];
    }
    __syncthreads();
    // 56 outputs: q = global j (0..7), k = head
    if (tid < 56) {
        int q = tid / 7, k = tid - 7 * q;
        int jgq = q >> 2, jl = q & 3;
        float v = red[jgq * 4 + 0][jl * 7 + k] + red[jgq * 4 + 1][jl * 7 + k]
                + red[jgq * 4 + 2][jl * 7 + k] + red[jgq * 4 + 3][jl * 7 + k];
        int e = b * 64 + i * 8 + q;
        float mf = g_mask[e];
        out[e * 7 + k] = (mf != 0.f) ? (v + sbias[k]) : 0.f;
    }
}

// ============================================================
// fallback zero
// ============================================================
__global__ void zero_kernel(float* __restrict__ out, int n0, int n1)
{
    int idx = n0 + blockIdx.x * blockDim.x + threadIdx.x;
    if (idx < n1) out[idx] = 0.0f;
}

// ============================================================
extern "C" void kernel_launch(void* const* d_in, const int* in_sizes, int n_in,
                              void* d_out, int out_size)
{
    const float* img    = (const float*)d_in[0];
    const float* pos    = (const float*)d_in[1];
    /* d_in[2] = rot, unused */
    const float* Wpatch = (const float*)d_in[3];
    const float* bpatch = (const float*)d_in[4];
    const float* W1a    = (const float*)d_in[5];
    const float* W1b    = (const float*)d_in[6];
    const float* b1     = (const float*)d_in[7];
    const float* W2     = (const float*)d_in[8];
    const float* b2     = (const float*)d_in[9];
    const float* Wp     = (const float*)d_in[10];
    const float* bp     = (const float*)d_in[11];
    const float* Wpv    = (const float*)d_in[12];
    const float* bpv    = (const float*)d_in[13];
    const float* Wr     = (const float*)d_in[14];
    const float* br     = (const float*)d_in[15];
    const float* Wrv    = (const float*)d_in[16];
    const float* brv    = (const float*)d_in[17];
    float* out = (float*)d_out;

    cudaFuncSetAttribute(patch_mma_kernel,
                         cudaFuncAttributeMaxDynamicSharedMemorySize, G_SMEM);
    cudaFuncSetAttribute(ag_mma_kernel,
                         cudaFuncAttributeMaxDynamicSharedMemorySize, G_SMEM);

    // fused prep
    prep_all_kernel<<<PB_TOTAL, 256>>>(pos, Wpatch, W1a, W1b, W2, b2,
                                       Wp, bp, Wpv, bpv, Wr, br, Wrv, brv, out);
    // patch embedding GEMM (A prefetch depth 2)
    patch_mma_kernel<<<dim3(C_ / 128, NP / 128), 256, G_SMEM>>>(img, bpatch);
    // a|g GEMM (+b1 folded into a)
    ag_mma_kernel<<<dim3(NAG / 128, NP / 128), 256, G_SMEM>>>(b1);
    // fused edge MLP + heads
    edge_b_kernel<<<256, 256>>>(out);
    // defensive zero
    int n1 = out_size, n0 = NODE0 + NODEZ;
    if (n1 > n0)
        zero_kernel<<<(n1 - n0 + 255) / 256, 256>>>(out, n0, n1);
}

// round 15
// speedup vs baseline: 1.1117x; 1.1117x over previous
#include <cuda_runtime.h>
#include <cuda_bf16.h>
#include <cuda_fp16.h>
#include <cstdint>

#define B_    32
#define N_    8
#define CIN   3
#define HWD   224
#define PATCH 32
#define S_    49
#define C_    384
#define HM_   512
#define CO_   256
#define NP    12544
#define KCONV 3072
#define NE    2048
#define NAG   1024
#define NODE0 (NE * 7 + NE)
#define NODEZ (B_ * N_ * 3600)

// ---- scratch (static device globals; no allocation) ----
__device__ __align__(16) __half g_Wph[C_ * KCONV];
__device__ __align__(16) __half g_W1t_h[NAG * C_];
__device__ __align__(16) __half g_feats_h[NP * C_];
__device__ __align__(16) __half g_a[NP * HM_];     // includes +b1
__device__ __align__(16) __half g_g[NP * HM_];
__device__ float g_mask[NE];
__device__ float g_W2h[HM_ * 7];
__device__ float g_bias7[7];

// ---- helpers ----
__device__ __forceinline__ uint32_t smem_to_u32(const void* p) {
    uint32_t a;
    asm("{ .reg .u64 t; cvta.to.shared.u64 t, %1; cvt.u32.u64 %0, t; }" : "=r"(a) : "l"(p));
    return a;
}
__device__ __forceinline__ void cp16(uint32_t dst, const void* src) {
    asm volatile("cp.async.cg.shared.global [%0], [%1], 16;" :: "r"(dst), "l"(src));
}
#define CP_COMMIT() asm volatile("cp.async.commit_group;" ::: "memory")
#define CP_WAIT1()  asm volatile("cp.async.wait_group 1;" ::: "memory")
#define CP_WAIT0()  asm volatile("cp.async.wait_group 0;" ::: "memory")

__device__ __forceinline__ void ldm4(uint32_t* r, uint32_t addr) {
    asm volatile("ldmatrix.sync.aligned.m8n8.x4.shared.b16 {%0,%1,%2,%3}, [%4];"
                 : "=r"(r[0]), "=r"(r[1]), "=r"(r[2]), "=r"(r[3]) : "r"(addr));
}
__device__ __forceinline__ void mma_f16(float* c, const uint32_t* a,
                                        uint32_t b0, uint32_t b1) {
    asm volatile(
        "mma.sync.aligned.m16n8k16.row.col.f32.f16.f16.f32 "
        "{%0,%1,%2,%3}, {%4,%5,%6,%7}, {%8,%9}, {%0,%1,%2,%3};"
        : "+f"(c[0]), "+f"(c[1]), "+f"(c[2]), "+f"(c[3])
        : "r"(a[0]), "r"(a[1]), "r"(a[2]), "r"(a[3]), "r"(b0), "r"(b1));
}
__device__ __forceinline__ uint32_t h2pack(float x, float y) {
    __half2 h = __floats2half2_rn(x, y);
    return *reinterpret_cast<uint32_t*>(&h);
}

// smem rows: 32 fp16 (64B) padded to 80B (conflict-free mod 128)
#define ROWB    80
#define TILE_B  (128 * ROWB)
#define G_STAGE  (2 * TILE_B)
#define G_SMEM   (3 * G_STAGE)
#define GOFF_A   0
#define GOFF_B   TILE_B

// ============================================================
// Fused prep: w2h | mask | wp | w1-transpose | node-zeros
// ============================================================
#define PB_W2H  64
#define PB_MASK 8
#define PB_WP   ((C_ * KCONV / 4) / 256)
#define PB_W1T  ((NAG / 64) * (C_ / 64))
#define PB_ZERO (NODEZ / (256 * 16))
#define PB_TOTAL (PB_W2H + PB_MASK + PB_WP + PB_W1T + PB_ZERO)

__device__ __forceinline__ float head_w(int o, int k,
                                        const float* Wph, const float* Wpv,
                                        const float* Wr, const float* Wrv)
{
    if (k < 2) return Wph[o * 2 + k];
    if (k < 4) return Wpv[o * 2 + (k - 2)];
    if (k < 6) return Wr[o * 2 + (k - 4)];
    return Wrv[o];
}

__global__ void __launch_bounds__(256)
prep_all_kernel(const float* __restrict__ pos,
                const float* __restrict__ Wp,
                const float* __restrict__ W1a, const float* __restrict__ W1b,
                const float* __restrict__ W2,  const float* __restrict__ b2,
                const float* __restrict__ Wph, const float* __restrict__ bph,
                const float* __restrict__ Wpv, const float* __restrict__ bpv,
                const float* __restrict__ Wr,  const float* __restrict__ br,
                const float* __restrict__ Wrv, const float* __restrict__ brv,
                float* __restrict__ out)
{
    __shared__ float ts[64][65];
    float (*sW)[7] = (float (*)[7])&ts[0][0];
    int bid = blockIdx.x;
    const int tid = threadIdx.x;

    if (bid < PB_W2H) {
        const int lane = tid & 31, wid = tid >> 5;
        if (tid < CO_) {
#pragma unroll
            for (int k = 0; k < 7; k++)
                sW[tid][k] = head_w(tid, k, Wph, Wpv, Wr, Wrv);
        }
        __syncthreads();
        const int h = bid * 8 + wid;
        float acc[7] = {0, 0, 0, 0, 0, 0, 0};
#pragma unroll
        for (int t = 0; t < 8; t++) {
            int o = lane + 32 * t;
            float w2 = W2[h * CO_ + o];
#pragma unroll
            for (int k = 0; k < 7; k++)
                acc[k] = fmaf(w2, sW[o][k], acc[k]);
        }
#pragma unroll
        for (int k = 0; k < 7; k++) {
#pragma unroll
            for (int off = 16; off; off >>= 1)
                acc[k] += __shfl_down_sync(0xffffffffu, acc[k], off);
        }
        if (lane == 0) {
#pragma unroll
            for (int k = 0; k < 7; k++)
                g_W2h[h * 7 + k] = acc[k] * (1.0f / 49.0f);
        }
        if (bid == 0 && tid < 7) {
            float sum = 0.f;
            for (int o = 0; o < CO_; o++)
                sum = fmaf(b2[o], sW[o][tid], sum);
            float bb = (tid < 2) ? bph[tid] : (tid < 4) ? bpv[tid - 2]
                     : (tid < 6) ? br[tid - 4] : brv[0];
            g_bias7[tid] = sum + bb;
        }
        return;
    }
    bid -= PB_W2H;

    if (bid < PB_MASK) {
        int e = bid * 256 + tid;
        int b = e >> 6, i = (e >> 3) & 7, j = e & 7;
        float xi = pos[(b * N_ + i) * 3 + 0], yi = pos[(b * N_ + i) * 3 + 1];
        float xj = pos[(b * N_ + j) * 3 + 0], yj = pos[(b * N_ + j) * 3 + 1];
        float dx = xi - xj, dy = yi - yj;
        float d2 = __fadd_rn(__fmul_rn(dx, dx), __fmul_rn(dy, dy));
        float m = (d2 < 0.25f && i != j) ? 1.0f : 0.0f;
        g_mask[e] = m;
        out[NE * 7 + e] = m;
        return;
    }
    bid -= PB_MASK;

    if (bid < PB_WP) {
        int i4 = bid * 256 + tid;
        float4 v = *(const float4*)&Wp[(long)i4 * 4];
        *(uint2*)&g_Wph[(long)i4 * 4] = make_uint2(h2pack(v.x, v.y), h2pack(v.z, v.w));
        return;
    }
    bid -= PB_WP;

    if (bid < PB_W1T) {
        int nt = bid / (C_ / 64);
        int kt = bid - nt * (C_ / 64);
        int n0 = nt * 64, k0 = kt * 64;
#pragma unroll
        for (int it = 0; it < 16; it++) {
            int idx = it * 256 + tid;
            int kk = idx >> 6, nn = idx & 63;
            int n = n0 + nn;
            float v = (n < HM_) ? W1a[(k0 + kk) * HM_ + n]
                                : W1b[(k0 + kk) * HM_ + (n - HM_)];
            ts[kk][nn] = v;
        }
        __syncthreads();
#pragma unroll
        for (int it = 0; it < 16; it++) {
            int idx = it * 256 + tid;
            int nn = idx >> 6, kk = idx & 63;
            g_W1t_h[(n0 + nn) * C_ + k0 + kk] = __float2half_rn(ts[kk][nn]);
        }
        return;
    }
    bid -= PB_W1T;

    {   // node_preds zeros
        int base = NODE0 + (bid * 256 + tid) * 16;
        float4 z = make_float4(0.f, 0.f, 0.f, 0.f);
        *(float4*)&out[base]      = z;
        *(float4*)&out[base + 4]  = z;
        *(float4*)&out[base + 8]  = z;
        *(float4*)&out[base + 12] = z;
    }
}

// ============================================================
// Patch GEMM: A = fp32 img, depth-2 prefetch with convert-at-load
// (hreg[2][8] uint32 = 16 regs, same as R13's single buffer).
// B: 3-stage cp.async. grid (3, 98).
// ============================================================
__global__ void __launch_bounds__(256, 2)
patch_mma_kernel(const float* __restrict__ img, const float* __restrict__ bp)
{
    extern __shared__ __align__(128) char smem[];
    const uint32_t sb = smem_to_u32(smem);
    const int tid = threadIdx.x, lane = tid & 31, w = tid >> 5;
    const int wm = w >> 2, wn = w & 3;
    const int bn = blockIdx.x * 128, bm = blockIdx.y * 128;

    const int lrow = tid >> 1, lseg = tid & 1;
    int abase;
    {
        int p  = bm + lrow;
        int n  = p / 49;
        int s  = p - n * 49;
        int py = s / 7, px = s - py * 7;
        abase = (n * CIN * HWD + py * PATCH) * HWD + px * PATCH + lseg * 16;
    }
    const long brow = (long)(bn + lrow) * KCONV + lseg * 16;

    float acc[4][4][4];
#pragma unroll
    for (int mi = 0; mi < 4; mi++)
#pragma unroll
        for (int ni = 0; ni < 4; ni++)
#pragma unroll
            for (int t = 0; t < 4; t++) acc[mi][ni][t] = 0.f;

    uint32_t hreg[2][8];   // converted fp16 pairs, 16 regs total

    auto ldA = [&](int c, int buf) {
        int k  = c * 32;
        int ci = k >> 10, rem = k & 1023, y = rem >> 5;
        const float4* src = (const float4*)(img + abase + ci * (HWD * HWD) + y * HWD);
        float4 v0 = src[0], v1 = src[1], v2 = src[2], v3 = src[3];
        hreg[buf][0] = h2pack(v0.x, v0.y);
        hreg[buf][1] = h2pack(v0.z, v0.w);
        hreg[buf][2] = h2pack(v1.x, v1.y);
        hreg[buf][3] = h2pack(v1.z, v1.w);
        hreg[buf][4] = h2pack(v2.x, v2.y);
        hreg[buf][5] = h2pack(v2.z, v2.w);
        hreg[buf][6] = h2pack(v3.x, v3.y);
        hreg[buf][7] = h2pack(v3.z, v3.w);
    };
    auto stA = [&](int st, int buf) {
        uint32_t ad = sb + st * G_STAGE + GOFF_A + lrow * ROWB + lseg * 32;
        asm volatile("st.shared.v4.b32 [%0], {%1,%2,%3,%4};"
                     :: "r"(ad), "r"(hreg[buf][0]), "r"(hreg[buf][1]),
                        "r"(hreg[buf][2]), "r"(hreg[buf][3]));
        asm volatile("st.shared.v4.b32 [%0], {%1,%2,%3,%4};"
                     :: "r"(ad + 16), "r"(hreg[buf][4]), "r"(hreg[buf][5]),
                        "r"(hreg[buf][6]), "r"(hreg[buf][7]));
    };
    auto cpB = [&](int c, int st) {
        int k = c * 32;
        const __half* bsrc = g_Wph + brow + k;
        uint32_t bd = sb + st * G_STAGE + GOFF_B + lrow * ROWB + lseg * 32;
        cp16(bd, bsrc);
        cp16(bd + 16, bsrc + 8);
    };

    const int NC = KCONV / 32;   // 96
    ldA(0, 0);
    ldA(1, 1);
    cpB(0, 0); CP_COMMIT();
    cpB(1, 1); CP_COMMIT();

    int st = 0;
#pragma unroll 1
    for (int c = 0; c < NC; c++) {
        stA(st, c & 1);
        if (c + 1 < NC) { CP_WAIT1(); } else { CP_WAIT0(); }
        __syncthreads();
        if (c + 2 < NC) {
            int st2 = st + 2; if (st2 >= 3) st2 -= 3;
            cpB(c + 2, st2);
            CP_COMMIT();
            ldA(c + 2, c & 1);   // refill buffer just consumed
        }
        {
            const uint32_t sbase = sb + st * G_STAGE;
#pragma unroll
            for (int step = 0; step < 2; step++) {
                const uint32_t co = (uint32_t)(step * 32 + (lane >> 4) * 16);
                uint32_t bf[2][4];
#pragma unroll
                for (int nj = 0; nj < 2; nj++) {
                    uint32_t ro = (uint32_t)((wn * 32 + nj * 16 + (lane & 15)) * ROWB) + co;
                    ldm4(bf[nj], sbase + GOFF_B + ro);
                }
#pragma unroll
                for (int mi = 0; mi < 4; mi++) {
                    uint32_t af[4];
                    uint32_t ro = (uint32_t)((wm * 64 + mi * 16 + (lane & 15)) * ROWB) + co;
                    ldm4(af, sbase + GOFF_A + ro);
#pragma unroll
                    for (int ni = 0; ni < 4; ni++) {
                        int nj = ni >> 1, o = ni & 1;
                        mma_f16(acc[mi][ni], af, bf[nj][o], bf[nj][o + 2]);
                    }
                }
            }
        }
        if (++st == 3) st = 0;
    }

    const int r  = lane >> 2;
    const int cc = (lane & 3) * 2;
#pragma unroll
    for (int mi = 0; mi < 4; mi++) {
#pragma unroll
        for (int ni = 0; ni < 4; ni++) {
            int m0  = bm + wm * 64 + mi * 16 + r;
            int col = bn + wn * 32 + ni * 8 + cc;
            float b0 = bp[col], b1v = bp[col + 1];
            *(uint32_t*)&g_feats_h[(long)m0 * C_ + col] =
                h2pack(acc[mi][ni][0] + b0, acc[mi][ni][1] + b1v);
            *(uint32_t*)&g_feats_h[(long)(m0 + 8) * C_ + col] =
                h2pack(acc[mi][ni][2] + b0, acc[mi][ni][3] + b1v);
        }
    }
}

// ============================================================
// a|g GEMM: fp16 1-pass, 3-stage; epilogue stores fp16 (+b1 into a)
// grid (8, 98)
// ============================================================
__global__ void __launch_bounds__(256, 2)
ag_mma_kernel(const float* __restrict__ b1)
{
    extern __shared__ __align__(128) char smem[];
    const uint32_t sb = smem_to_u32(smem);
    const int tid = threadIdx.x, lane = tid & 31, w = tid >> 5;
    const int wm = w >> 2, wn = w & 3;
    const int bn = blockIdx.x * 128, bm = blockIdx.y * 128;

    const int lrow = tid >> 1, lseg = tid & 1;
    const long arow = (long)(bm + lrow) * C_ + lseg * 16;
    const long brow = (long)(bn + lrow) * C_ + lseg * 16;

    float acc[4][4][4];
#pragma unroll
    for (int mi = 0; mi < 4; mi++)
#pragma unroll
        for (int ni = 0; ni < 4; ni++)
#pragma unroll
            for (int t = 0; t < 4; t++) acc[mi][ni][t] = 0.f;

    auto cpAB = [&](int c, int st) {
        int k = c * 32;
        const __half* asrc = g_feats_h + arow + k;
        uint32_t ad = sb + st * G_STAGE + GOFF_A + lrow * ROWB + lseg * 32;
        cp16(ad, asrc);
        cp16(ad + 16, asrc + 8);
        const __half* bsrc = g_W1t_h + brow + k;
        uint32_t bd = sb + st * G_STAGE + GOFF_B + lrow * ROWB + lseg * 32;
        cp16(bd, bsrc);
        cp16(bd + 16, bsrc + 8);
    };

    const int NC = C_ / 32;   // 12
    cpAB(0, 0); CP_COMMIT();
    cpAB(1, 1); CP_COMMIT();

    int st = 0;
#pragma unroll 1
    for (int c = 0; c < NC; c++) {
        if (c + 1 < NC) { CP_WAIT1(); } else { CP_WAIT0(); }
        __syncthreads();
        if (c + 2 < NC) {
            int st2 = st + 2; if (st2 >= 3) st2 -= 3;
            cpAB(c + 2, st2);
            CP_COMMIT();
        }
        {
            const uint32_t sbase = sb + st * G_STAGE;
#pragma unroll
            for (int step = 0; step < 2; step++) {
                const uint32_t co = (uint32_t)(step * 32 + (lane >> 4) * 16);
                uint32_t bf[2][4];
#pragma unroll
                for (int nj = 0; nj < 2; nj++) {
                    uint32_t ro = (uint32_t)((wn * 32 + nj * 16 + (lane & 15)) * ROWB) + co;
                    ldm4(bf[nj], sbase + GOFF_B + ro);
                }
#pragma unroll
                for (int mi = 0; mi < 4; mi++) {
                    uint32_t af[4];
                    uint32_t ro = (uint32_t)((wm * 64 + mi * 16 + (lane & 15)) * ROWB) + co;
                    ldm4(af, sbase + GOFF_A + ro);
#pragma unroll
                    for (int ni = 0; ni < 4; ni++) {
                        int nj = ni >> 1, o = ni & 1;
                        mma_f16(acc[mi][ni], af, bf[nj][o], bf[nj][o + 2]);
                    }
                }
            }
        }
        if (++st == 3) st = 0;
    }

    const bool isA = (bn < HM_);
    __half* dst = isA ? g_a : g_g;
    const int nb = isA ? bn : bn - HM_;
    const int r  = lane >> 2;
    const int cc = (lane & 3) * 2;
#pragma unroll
    for (int mi = 0; mi < 4; mi++) {
#pragma unroll
        for (int ni = 0; ni < 4; ni++) {
            int m0  = bm + wm * 64 + mi * 16 + r;
            int col = nb + wn * 32 + ni * 8 + cc;
            float b0 = 0.f, b1v = 0.f;
            if (isA) { b0 = b1[col]; b1v = b1[col + 1]; }
            *(uint32_t*)&dst[(long)m0 * HM_ + col] =
                h2pack(acc[mi][ni][0] + b0, acc[mi][ni][1] + b1v);
            *(uint32_t*)&dst[(long)(m0 + 8) * HM_ + col] =
                h2pack(acc[mi][ni][2] + b0, acc[mi][ni][3] + b1v);
        }
    }
}

// ============================================================
// edge kernel (R13 proven version): block per (b, i, j-half);
// 256 threads, h-pair per thread
// ============================================================
__global__ void __launch_bounds__(256)
edge_b_kernel(float* __restrict__ out)
{
    __shared__ float red[8][28];
    __shared__ float sbias[7];

    const int blk = blockIdx.x;
    const int b   = blk >> 4;
    const int i   = (blk >> 1) & 7;
    const int jh  = blk & 1;
    const int tid = threadIdx.x, lane = tid & 31, wid = tid >> 5;

    if (tid < 7) sbias[tid] = g_bias7[tid];

    const __half2* __restrict__ ap =
        (const __half2*)(g_a + ((long)(b * 8 + i) * 49) * HM_) + tid;
    const __half2* __restrict__ gp =
        (const __half2*)(g_g + ((long)(b * 8 + jh * 4) * 49) * HM_) + tid;

    float2 acc[4];
#pragma unroll
    for (int j = 0; j < 4; j++) acc[j] = make_float2(0.f, 0.f);

#pragma unroll 7
    for (int s = 0; s < 49; s++) {
        const int so = s * 256;
        float2 av = __half22float2(ap[so]);
#pragma unroll
        for (int j = 0; j < 4; j++) {
            float2 gv = __half22float2(gp[j * (49 * 256) + so]);
            acc[j].x += fmaxf(av.x + gv.x, 0.f);
            acc[j].y += fmaxf(av.y + gv.y, 0.f);
        }
    }

    float wv[14];
#pragma unroll
    for (int k = 0; k < 14; k++) wv[k] = g_W2h[tid * 14 + k];

    __syncthreads();

    float pr[28];
#pragma unroll
    for (int q = 0; q < 4; q++)
#pragma unroll
        for (int k = 0; k < 7; k++)
            pr[q * 7 + k] = fmaf(acc[q].x, wv[k], acc[q].y * wv[7 + k]);
#pragma unroll
    for (int t = 0; t < 28; t++) {
#pragma unroll
        for (int off = 16; off; off >>= 1)
            pr[t] += __shfl_down_sync(0xffffffffu, pr[t], off);
    }
    if (lane == 0) {
#pragma unroll
        for (int t = 0; t < 28; t++) red[wid][t] = pr[t];
    }
    __syncthreads();
    if (tid < 28) {
        float v = 0.f;
#pragma unroll
        for (int ww = 0; ww < 8; ww++) v += red[ww][tid];
        int q = tid / 7, k = tid - 7 * q;
        int j = jh * 4 + q;
        int e = b * 64 + i * 8 + j;
        float mf = g_mask[e];
        out[e * 7 + k] = (mf != 0.f) ? (v + sbias[k]) : 0.f;
    }
}

// ============================================================
// fallback zero
// ============================================================
__global__ void zero_kernel(float* __restrict__ out, int n0, int n1)
{
    int idx = n0 + blockIdx.x * blockDim.x + threadIdx.x;
    if (idx < n1) out[idx] = 0.0f;
}

// ============================================================
extern "C" void kernel_launch(void* const* d_in, const int* in_sizes, int n_in,
                              void* d_out, int out_size)
{
    const float* img    = (const float*)d_in[0];
    const float* pos    = (const float*)d_in[1];
    /* d_in[2] = rot, unused */
    const float* Wpatch = (const float*)d_in[3];
    const float* bpatch = (const float*)d_in[4];
    const float* W1a    = (const float*)d_in[5];
    const float* W1b    = (const float*)d_in[6];
    const float* b1     = (const float*)d_in[7];
    const float* W2     = (const float*)d_in[8];
    const float* b2     = (const float*)d_in[9];
    const float* Wp     = (const float*)d_in[10];
    const float* bp     = (const float*)d_in[11];
    const float* Wpv    = (const float*)d_in[12];
    const float* bpv    = (const float*)d_in[13];
    const float* Wr     = (const float*)d_in[14];
    const float* br     = (const float*)d_in[15];
    const float* Wrv    = (const float*)d_in[16];
    const float* brv    = (const float*)d_in[17];
    float* out = (float*)d_out;

    cudaFuncSetAttribute(patch_mma_kernel,
                         cudaFuncAttributeMaxDynamicSharedMemorySize, G_SMEM);
    cudaFuncSetAttribute(ag_mma_kernel,
                         cudaFuncAttributeMaxDynamicSharedMemorySize, G_SMEM);

    // fused prep
    prep_all_kernel<<<PB_TOTAL, 256>>>(pos, Wpatch, W1a, W1b, W2, b2,
                                       Wp, bp, Wpv, bpv, Wr, br, Wrv, brv, out);
    // patch embedding GEMM (depth-2 A prefetch, convert-at-load)
    patch_mma_kernel<<<dim3(C_ / 128, NP / 128), 256, G_SMEM>>>(img, bpatch);
    // a|g GEMM (+b1 folded into a)
    ag_mma_kernel<<<dim3(NAG / 128, NP / 128), 256, G_SMEM>>>(b1);
    // fused edge MLP + heads (R13 proven config)
    edge_b_kernel<<<512, 256>>>(out);
    // defensive zero
    int n1 = out_size, n0 = NODE0 + NODEZ;
    if (n1 > n0)
        zero_kernel<<<(n1 - n0 + 255) / 256, 256>>>(out, n0, n1);
}

// round 16
// speedup vs baseline: 1.2927x; 1.1627x over previous
#include <cuda_runtime.h>
#include <cuda_bf16.h>
#include <cuda_fp16.h>
#include <cstdint>

#define B_    32
#define N_    8
#define CIN   3
#define HWD   224
#define PATCH 32
#define S_    49
#define C_    384
#define HM_   512
#define CO_   256
#define NP    12544
#define KCONV 3072
#define NE    2048
#define NAG   1024
#define NODE0 (NE * 7 + NE)
#define NODEZ (B_ * N_ * 3600)

// ---- scratch (static device globals; no allocation) ----
__device__ __align__(16) __half g_Wph[C_ * KCONV];
__device__ __align__(16) __half g_W1t_h[NAG * C_];
__device__ __align__(16) __half g_feats_h[NP * C_];
__device__ __align__(16) __half g_a[NP * HM_];     // includes +b1
__device__ __align__(16) __half g_g[NP * HM_];
__device__ float g_mask[NE];
__device__ float g_W2h[HM_ * 7];
__device__ float g_bias7[7];

// ---- helpers ----
__device__ __forceinline__ uint32_t smem_to_u32(const void* p) {
    uint32_t a;
    asm("{ .reg .u64 t; cvta.to.shared.u64 t, %1; cvt.u32.u64 %0, t; }" : "=r"(a) : "l"(p));
    return a;
}
__device__ __forceinline__ void cp16(uint32_t dst, const void* src) {
    asm volatile("cp.async.cg.shared.global [%0], [%1], 16;" :: "r"(dst), "l"(src));
}
#define CP_COMMIT() asm volatile("cp.async.commit_group;" ::: "memory")
#define CP_WAIT1()  asm volatile("cp.async.wait_group 1;" ::: "memory")
#define CP_WAIT0()  asm volatile("cp.async.wait_group 0;" ::: "memory")

__device__ __forceinline__ void ldm4(uint32_t* r, uint32_t addr) {
    asm volatile("ldmatrix.sync.aligned.m8n8.x4.shared.b16 {%0,%1,%2,%3}, [%4];"
                 : "=r"(r[0]), "=r"(r[1]), "=r"(r[2]), "=r"(r[3]) : "r"(addr));
}
__device__ __forceinline__ void mma_f16(float* c, const uint32_t* a,
                                        uint32_t b0, uint32_t b1) {
    asm volatile(
        "mma.sync.aligned.m16n8k16.row.col.f32.f16.f16.f32 "
        "{%0,%1,%2,%3}, {%4,%5,%6,%7}, {%8,%9}, {%0,%1,%2,%3};"
        : "+f"(c[0]), "+f"(c[1]), "+f"(c[2]), "+f"(c[3])
        : "r"(a[0]), "r"(a[1]), "r"(a[2]), "r"(a[3]), "r"(b0), "r"(b1));
}
__device__ __forceinline__ uint32_t h2pack(float x, float y) {
    __half2 h = __floats2half2_rn(x, y);
    return *reinterpret_cast<uint32_t*>(&h);
}

// smem rows: 32 fp16 (64B) padded to 80B (conflict-free mod 128)
#define ROWB    80
#define TILE_B  (128 * ROWB)
#define G_STAGE  (2 * TILE_B)
#define G_SMEM   (3 * G_STAGE)
#define GOFF_A   0
#define GOFF_B   TILE_B

// ============================================================
// Fused prep: w2h | mask | wp | w1-transpose | node-zeros
// ============================================================
#define PB_W2H  64
#define PB_MASK 8
#define PB_WP   ((C_ * KCONV / 4) / 256)
#define PB_W1T  ((NAG / 64) * (C_ / 64))
#define PB_ZERO (NODEZ / (256 * 16))
#define PB_TOTAL (PB_W2H + PB_MASK + PB_WP + PB_W1T + PB_ZERO)

__device__ __forceinline__ float head_w(int o, int k,
                                        const float* Wph, const float* Wpv,
                                        const float* Wr, const float* Wrv)
{
    if (k < 2) return Wph[o * 2 + k];
    if (k < 4) return Wpv[o * 2 + (k - 2)];
    if (k < 6) return Wr[o * 2 + (k - 4)];
    return Wrv[o];
}

__global__ void __launch_bounds__(256)
prep_all_kernel(const float* __restrict__ pos,
                const float* __restrict__ Wp,
                const float* __restrict__ W1a, const float* __restrict__ W1b,
                const float* __restrict__ W2,  const float* __restrict__ b2,
                const float* __restrict__ Wph, const float* __restrict__ bph,
                const float* __restrict__ Wpv, const float* __restrict__ bpv,
                const float* __restrict__ Wr,  const float* __restrict__ br,
                const float* __restrict__ Wrv, const float* __restrict__ brv,
                float* __restrict__ out)
{
    __shared__ float ts[64][65];
    float (*sW)[7] = (float (*)[7])&ts[0][0];
    int bid = blockIdx.x;
    const int tid = threadIdx.x;

    if (bid < PB_W2H) {
        const int lane = tid & 31, wid = tid >> 5;
        if (tid < CO_) {
#pragma unroll
            for (int k = 0; k < 7; k++)
                sW[tid][k] = head_w(tid, k, Wph, Wpv, Wr, Wrv);
        }
        __syncthreads();
        const int h = bid * 8 + wid;
        float acc[7] = {0, 0, 0, 0, 0, 0, 0};
#pragma unroll
        for (int t = 0; t < 8; t++) {
            int o = lane + 32 * t;
            float w2 = W2[h * CO_ + o];
#pragma unroll
            for (int k = 0; k < 7; k++)
                acc[k] = fmaf(w2, sW[o][k], acc[k]);
        }
#pragma unroll
        for (int k = 0; k < 7; k++) {
#pragma unroll
            for (int off = 16; off; off >>= 1)
                acc[k] += __shfl_down_sync(0xffffffffu, acc[k], off);
        }
        if (lane == 0) {
#pragma unroll
            for (int k = 0; k < 7; k++)
                g_W2h[h * 7 + k] = acc[k] * (1.0f / 49.0f);
        }
        if (bid == 0 && tid < 7) {
            float sum = 0.f;
            for (int o = 0; o < CO_; o++)
                sum = fmaf(b2[o], sW[o][tid], sum);
            float bb = (tid < 2) ? bph[tid] : (tid < 4) ? bpv[tid - 2]
                     : (tid < 6) ? br[tid - 4] : brv[0];
            g_bias7[tid] = sum + bb;
        }
        return;
    }
    bid -= PB_W2H;

    if (bid < PB_MASK) {
        int e = bid * 256 + tid;
        int b = e >> 6, i = (e >> 3) & 7, j = e & 7;
        float xi = pos[(b * N_ + i) * 3 + 0], yi = pos[(b * N_ + i) * 3 + 1];
        float xj = pos[(b * N_ + j) * 3 + 0], yj = pos[(b * N_ + j) * 3 + 1];
        float dx = xi - xj, dy = yi - yj;
        float d2 = __fadd_rn(__fmul_rn(dx, dx), __fmul_rn(dy, dy));
        float m = (d2 < 0.25f && i != j) ? 1.0f : 0.0f;
        g_mask[e] = m;
        out[NE * 7 + e] = m;
        return;
    }
    bid -= PB_MASK;

    if (bid < PB_WP) {
        int i4 = bid * 256 + tid;
        float4 v = *(const float4*)&Wp[(long)i4 * 4];
        *(uint2*)&g_Wph[(long)i4 * 4] = make_uint2(h2pack(v.x, v.y), h2pack(v.z, v.w));
        return;
    }
    bid -= PB_WP;

    if (bid < PB_W1T) {
        int nt = bid / (C_ / 64);
        int kt = bid - nt * (C_ / 64);
        int n0 = nt * 64, k0 = kt * 64;
#pragma unroll
        for (int it = 0; it < 16; it++) {
            int idx = it * 256 + tid;
            int kk = idx >> 6, nn = idx & 63;
            int n = n0 + nn;
            float v = (n < HM_) ? W1a[(k0 + kk) * HM_ + n]
                                : W1b[(k0 + kk) * HM_ + (n - HM_)];
            ts[kk][nn] = v;
        }
        __syncthreads();
#pragma unroll
        for (int it = 0; it < 16; it++) {
            int idx = it * 256 + tid;
            int nn = idx >> 6, kk = idx & 63;
            g_W1t_h[(n0 + nn) * C_ + k0 + kk] = __float2half_rn(ts[kk][nn]);
        }
        return;
    }
    bid -= PB_W1T;

    {   // node_preds zeros
        int base = NODE0 + (bid * 256 + tid) * 16;
        float4 z = make_float4(0.f, 0.f, 0.f, 0.f);
        *(float4*)&out[base]      = z;
        *(float4*)&out[base + 4]  = z;
        *(float4*)&out[base + 8]  = z;
        *(float4*)&out[base + 12] = z;
    }
}

// ============================================================
// Patch GEMM: depth-2 A prefetch with COMPILE-TIME buffer/stage
// (manual 6x unroll; hA/hB are true registers). grid (3, 98).
// ============================================================
__global__ void __launch_bounds__(256, 2)
patch_mma_kernel(const float* __restrict__ img, const float* __restrict__ bp)
{
    extern __shared__ __align__(128) char smem[];
    const uint32_t sb = smem_to_u32(smem);
    const int tid = threadIdx.x, lane = tid & 31, w = tid >> 5;
    const int wm = w >> 2, wn = w & 3;
    const int bn = blockIdx.x * 128, bm = blockIdx.y * 128;

    const int lrow = tid >> 1, lseg = tid & 1;
    int abase;
    {
        int p  = bm + lrow;
        int n  = p / 49;
        int s  = p - n * 49;
        int py = s / 7, px = s - py * 7;
        abase = (n * CIN * HWD + py * PATCH) * HWD + px * PATCH + lseg * 16;
    }
    const long brow = (long)(bn + lrow) * KCONV + lseg * 16;

    float acc[4][4][4];
#pragma unroll
    for (int mi = 0; mi < 4; mi++)
#pragma unroll
        for (int ni = 0; ni < 4; ni++)
#pragma unroll
            for (int t = 0; t < 4; t++) acc[mi][ni][t] = 0.f;

    uint32_t hA[8], hB[8];

#define LDA_(c, H) do {                                                        \
    int k_  = (c) * 32;                                                        \
    int ci_ = k_ >> 10, rem_ = k_ & 1023, y_ = rem_ >> 5;                      \
    const float4* src_ = (const float4*)(img + abase + ci_ * (HWD * HWD)      \
                                         + y_ * HWD);                         \
    float4 v0_ = src_[0], v1_ = src_[1], v2_ = src_[2], v3_ = src_[3];         \
    H[0] = h2pack(v0_.x, v0_.y); H[1] = h2pack(v0_.z, v0_.w);                  \
    H[2] = h2pack(v1_.x, v1_.y); H[3] = h2pack(v1_.z, v1_.w);                  \
    H[4] = h2pack(v2_.x, v2_.y); H[5] = h2pack(v2_.z, v2_.w);                  \
    H[6] = h2pack(v3_.x, v3_.y); H[7] = h2pack(v3_.z, v3_.w);                  \
} while (0)

#define STA_(ST, H) do {                                                       \
    uint32_t ad_ = sb + (ST) * G_STAGE + GOFF_A + lrow * ROWB + lseg * 32;     \
    asm volatile("st.shared.v4.b32 [%0], {%1,%2,%3,%4};"                       \
                 :: "r"(ad_), "r"(H[0]), "r"(H[1]), "r"(H[2]), "r"(H[3]));     \
    asm volatile("st.shared.v4.b32 [%0], {%1,%2,%3,%4};"                       \
                 :: "r"(ad_ + 16), "r"(H[4]), "r"(H[5]), "r"(H[6]), "r"(H[7]));\
} while (0)

    auto cpB = [&](int c, int st) {
        int k = c * 32;
        const __half* bsrc = g_Wph + brow + k;
        uint32_t bd = sb + st * G_STAGE + GOFF_B + lrow * ROWB + lseg * 32;
        cp16(bd, bsrc);
        cp16(bd + 16, bsrc + 8);
    };

    auto mma_sec = [&](uint32_t sbase) {
#pragma unroll
        for (int step = 0; step < 2; step++) {
            const uint32_t co = (uint32_t)(step * 32 + (lane >> 4) * 16);
            uint32_t bf[2][4];
#pragma unroll
            for (int nj = 0; nj < 2; nj++) {
                uint32_t ro = (uint32_t)((wn * 32 + nj * 16 + (lane & 15)) * ROWB) + co;
                ldm4(bf[nj], sbase + GOFF_B + ro);
            }
#pragma unroll
            for (int mi = 0; mi < 4; mi++) {
                uint32_t af[4];
                uint32_t ro = (uint32_t)((wm * 64 + mi * 16 + (lane & 15)) * ROWB) + co;
                ldm4(af, sbase + GOFF_A + ro);
#pragma unroll
                for (int ni = 0; ni < 4; ni++) {
                    int nj = ni >> 1, o = ni & 1;
                    mma_f16(acc[mi][ni], af, bf[nj][o], bf[nj][o + 2]);
                }
            }
        }
    };

#define PBODY(c, ST, H) do {                                                   \
    STA_(ST, H);                                                               \
    if ((c) + 1 < NC) { CP_WAIT1(); } else { CP_WAIT0(); }                     \
    __syncthreads();                                                           \
    if ((c) + 2 < NC) {                                                        \
        cpB((c) + 2, ((ST) + 2) % 3);                                          \
        CP_COMMIT();                                                           \
        LDA_((c) + 2, H);                                                      \
    }                                                                          \
    mma_sec(sb + (ST) * G_STAGE);                                              \
} while (0)

    const int NC = KCONV / 32;   // 96, divisible by 6
    LDA_(0, hA);
    LDA_(1, hB);
    cpB(0, 0); CP_COMMIT();
    cpB(1, 1); CP_COMMIT();

#pragma unroll 1
    for (int cb = 0; cb < NC; cb += 6) {
        PBODY(cb + 0, 0, hA);
        PBODY(cb + 1, 1, hB);
        PBODY(cb + 2, 2, hA);
        PBODY(cb + 3, 0, hB);
        PBODY(cb + 4, 1, hA);
        PBODY(cb + 5, 2, hB);
    }
#undef PBODY
#undef STA_
#undef LDA_

    const int r  = lane >> 2;
    const int cc = (lane & 3) * 2;
#pragma unroll
    for (int mi = 0; mi < 4; mi++) {
#pragma unroll
        for (int ni = 0; ni < 4; ni++) {
            int m0  = bm + wm * 64 + mi * 16 + r;
            int col = bn + wn * 32 + ni * 8 + cc;
            float b0 = bp[col], b1v = bp[col + 1];
            *(uint32_t*)&g_feats_h[(long)m0 * C_ + col] =
                h2pack(acc[mi][ni][0] + b0, acc[mi][ni][1] + b1v);
            *(uint32_t*)&g_feats_h[(long)(m0 + 8) * C_ + col] =
                h2pack(acc[mi][ni][2] + b0, acc[mi][ni][3] + b1v);
        }
    }
}

// ============================================================
// a|g GEMM: fp16 1-pass, 3-stage; epilogue stores fp16 (+b1 into a)
// grid (8, 98)
// ============================================================
__global__ void __launch_bounds__(256, 2)
ag_mma_kernel(const float* __restrict__ b1)
{
    extern __shared__ __align__(128) char smem[];
    const uint32_t sb = smem_to_u32(smem);
    const int tid = threadIdx.x, lane = tid & 31, w = tid >> 5;
    const int wm = w >> 2, wn = w & 3;
    const int bn = blockIdx.x * 128, bm = blockIdx.y * 128;

    const int lrow = tid >> 1, lseg = tid & 1;
    const long arow = (long)(bm + lrow) * C_ + lseg * 16;
    const long brow = (long)(bn + lrow) * C_ + lseg * 16;

    float acc[4][4][4];
#pragma unroll
    for (int mi = 0; mi < 4; mi++)
#pragma unroll
        for (int ni = 0; ni < 4; ni++)
#pragma unroll
            for (int t = 0; t < 4; t++) acc[mi][ni][t] = 0.f;

    auto cpAB = [&](int c, int st) {
        int k = c * 32;
        const __half* asrc = g_feats_h + arow + k;
        uint32_t ad = sb + st * G_STAGE + GOFF_A + lrow * ROWB + lseg * 32;
        cp16(ad, asrc);
        cp16(ad + 16, asrc + 8);
        const __half* bsrc = g_W1t_h + brow + k;
        uint32_t bd = sb + st * G_STAGE + GOFF_B + lrow * ROWB + lseg * 32;
        cp16(bd, bsrc);
        cp16(bd + 16, bsrc + 8);
    };

    const int NC = C_ / 32;   // 12
    cpAB(0, 0); CP_COMMIT();
    cpAB(1, 1); CP_COMMIT();

    int st = 0;
#pragma unroll 1
    for (int c = 0; c < NC; c++) {
        if (c + 1 < NC) { CP_WAIT1(); } else { CP_WAIT0(); }
        __syncthreads();
        if (c + 2 < NC) {
            int st2 = st + 2; if (st2 >= 3) st2 -= 3;
            cpAB(c + 2, st2);
            CP_COMMIT();
        }
        {
            const uint32_t sbase = sb + st * G_STAGE;
#pragma unroll
            for (int step = 0; step < 2; step++) {
                const uint32_t co = (uint32_t)(step * 32 + (lane >> 4) * 16);
                uint32_t bf[2][4];
#pragma unroll
                for (int nj = 0; nj < 2; nj++) {
                    uint32_t ro = (uint32_t)((wn * 32 + nj * 16 + (lane & 15)) * ROWB) + co;
                    ldm4(bf[nj], sbase + GOFF_B + ro);
                }
#pragma unroll
                for (int mi = 0; mi < 4; mi++) {
                    uint32_t af[4];
                    uint32_t ro = (uint32_t)((wm * 64 + mi * 16 + (lane & 15)) * ROWB) + co;
                    ldm4(af, sbase + GOFF_A + ro);
#pragma unroll
                    for (int ni = 0; ni < 4; ni++) {
                        int nj = ni >> 1, o = ni & 1;
                        mma_f16(acc[mi][ni], af, bf[nj][o], bf[nj][o + 2]);
                    }
                }
            }
        }
        if (++st == 3) st = 0;
    }

    const bool isA = (bn < HM_);
    __half* dst = isA ? g_a : g_g;
    const int nb = isA ? bn : bn - HM_;
    const int r  = lane >> 2;
    const int cc = (lane & 3) * 2;
#pragma unroll
    for (int mi = 0; mi < 4; mi++) {
#pragma unroll
        for (int ni = 0; ni < 4; ni++) {
            int m0  = bm + wm * 64 + mi * 16 + r;
            int col = nb + wn * 32 + ni * 8 + cc;
            float b0 = 0.f, b1v = 0.f;
            if (isA) { b0 = b1[col]; b1v = b1[col + 1]; }
            *(uint32_t*)&dst[(long)m0 * HM_ + col] =
                h2pack(acc[mi][ni][0] + b0, acc[mi][ni][1] + b1v);
            *(uint32_t*)&dst[(long)(m0 + 8) * HM_ + col] =
                h2pack(acc[mi][ni][2] + b0, acc[mi][ni][3] + b1v);
        }
    }
}

// ============================================================
// edge kernel (proven): block per (b, i, j-half); 256 threads
// ============================================================
__global__ void __launch_bounds__(256)
edge_b_kernel(float* __restrict__ out)
{
    __shared__ float red[8][28];
    __shared__ float sbias[7];

    const int blk = blockIdx.x;
    const int b   = blk >> 4;
    const int i   = (blk >> 1) & 7;
    const int jh  = blk & 1;
    const int tid = threadIdx.x, lane = tid & 31, wid = tid >> 5;

    if (tid < 7) sbias[tid] = g_bias7[tid];

    const __half2* __restrict__ ap =
        (const __half2*)(g_a + ((long)(b * 8 + i) * 49) * HM_) + tid;
    const __half2* __restrict__ gp =
        (const __half2*)(g_g + ((long)(b * 8 + jh * 4) * 49) * HM_) + tid;

    float2 acc[4];
#pragma unroll
    for (int j = 0; j < 4; j++) acc[j] = make_float2(0.f, 0.f);

#pragma unroll 7
    for (int s = 0; s < 49; s++) {
        const int so = s * 256;
        float2 av = __half22float2(ap[so]);
#pragma unroll
        for (int j = 0; j < 4; j++) {
            float2 gv = __half22float2(gp[j * (49 * 256) + so]);
            acc[j].x += fmaxf(av.x + gv.x, 0.f);
            acc[j].y += fmaxf(av.y + gv.y, 0.f);
        }
    }

    float wv[14];
#pragma unroll
    for (int k = 0; k < 14; k++) wv[k] = g_W2h[tid * 14 + k];

    __syncthreads();

    float pr[28];
#pragma unroll
    for (int q = 0; q < 4; q++)
#pragma unroll
        for (int k = 0; k < 7; k++)
            pr[q * 7 + k] = fmaf(acc[q].x, wv[k], acc[q].y * wv[7 + k]);
#pragma unroll
    for (int t = 0; t < 28; t++) {
#pragma unroll
        for (int off = 16; off; off >>= 1)
            pr[t] += __shfl_down_sync(0xffffffffu, pr[t], off);
    }
    if (lane == 0) {
#pragma unroll
        for (int t = 0; t < 28; t++) red[wid][t] = pr[t];
    }
    __syncthreads();
    if (tid < 28) {
        float v = 0.f;
#pragma unroll
        for (int ww = 0; ww < 8; ww++) v += red[ww][tid];
        int q = tid / 7, k = tid - 7 * q;
        int j = jh * 4 + q;
        int e = b * 64 + i * 8 + j;
        float mf = g_mask[e];
        out[e * 7 + k] = (mf != 0.f) ? (v + sbias[k]) : 0.f;
    }
}

// ============================================================
// fallback zero
// ============================================================
__global__ void zero_kernel(float* __restrict__ out, int n0, int n1)
{
    int idx = n0 + blockIdx.x * blockDim.x + threadIdx.x;
    if (idx < n1) out[idx] = 0.0f;
}

// ============================================================
extern "C" void kernel_launch(void* const* d_in, const int* in_sizes, int n_in,
                              void* d_out, int out_size)
{
    const float* img    = (const float*)d_in[0];
    const float* pos    = (const float*)d_in[1];
    /* d_in[2] = rot, unused */
    const float* Wpatch = (const float*)d_in[3];
    const float* bpatch = (const float*)d_in[4];
    const float* W1a    = (const float*)d_in[5];
    const float* W1b    = (const float*)d_in[6];
    const float* b1     = (const float*)d_in[7];
    const float* W2     = (const float*)d_in[8];
    const float* b2     = (const float*)d_in[9];
    const float* Wp     = (const float*)d_in[10];
    const float* bp     = (const float*)d_in[11];
    const float* Wpv    = (const float*)d_in[12];
    const float* bpv    = (const float*)d_in[13];
    const float* Wr     = (const float*)d_in[14];
    const float* br     = (const float*)d_in[15];
    const float* Wrv    = (const float*)d_in[16];
    const float* brv    = (const float*)d_in[17];
    float* out = (float*)d_out;

    cudaFuncSetAttribute(patch_mma_kernel,
                         cudaFuncAttributeMaxDynamicSharedMemorySize, G_SMEM);
    cudaFuncSetAttribute(ag_mma_kernel,
                         cudaFuncAttributeMaxDynamicSharedMemorySize, G_SMEM);

    // fused prep
    prep_all_kernel<<<PB_TOTAL, 256>>>(pos, Wpatch, W1a, W1b, W2, b2,
                                       Wp, bp, Wpv, bpv, Wr, br, Wrv, brv, out);
    // patch embedding GEMM (register-resident depth-2 prefetch)
    patch_mma_kernel<<<dim3(C_ / 128, NP / 128), 256, G_SMEM>>>(img, bpatch);
    // a|g GEMM (+b1 folded into a)
    ag_mma_kernel<<<dim3(NAG / 128, NP / 128), 256, G_SMEM>>>(b1);
    // fused edge MLP + heads
    edge_b_kernel<<<512, 256>>>(out);
    // defensive zero
    int n1 = out_size, n0 = NODE0 + NODEZ;
    if (n1 > n0)
        zero_kernel<<<(n1 - n0 + 255) / 256, 256>>>(out, n0, n1);
}